// round 2
// baseline (speedup 1.0000x reference)
#include <cuda_runtime.h>
#include <cuda_bf16.h>

#define T_STEPS 10
#define NN      50000
#define F_INN   2
#define F_OUTN  16
#define HID     32
#define NE      800000

#define BN      128     // nodes per block in main kernel
#define NTHR    256

// ---------------- device scratch (no allocations allowed) ----------------
__device__ float g_deg [NN];
__device__ float g_dinv[NN];
__device__ float g_xs  [NN * 20];   // dinv[n] * x, laid out [n][t*2+k]
__device__ float g_acc [NN * 20];   // aggregated (seeded with self-loop term)

// ---------------- small prep kernels ----------------
__global__ void k_init_deg() {
    int n = blockIdx.x * blockDim.x + threadIdx.x;
    if (n < NN) g_deg[n] = 1.0f;          // self-loop
}

__global__ void k_count(const int* __restrict__ ei) {
    int e = blockIdx.x * blockDim.x + threadIdx.x;
    if (e < NE) atomicAdd(&g_deg[ei[NE + e]], 1.0f);
}

__global__ void k_dinv() {
    int n = blockIdx.x * blockDim.x + threadIdx.x;
    if (n < NN) g_dinv[n] = rsqrtf(g_deg[n]);   // deg >= 1 always
}

// xs[n][t*2+k] = dinv[n] * x[t][n][k]; acc seeded identically (self-loop msg)
__global__ void k_xs(const float* __restrict__ x) {
    int idx = blockIdx.x * blockDim.x + threadIdx.x;   // over T*N*2 = 1M
    if (idx < T_STEPS * NN * F_INN) {
        int k = idx & 1;
        int n = (idx >> 1) % NN;
        int t = idx / (NN * F_INN);
        float v = g_dinv[n] * x[idx];
        int o = n * 20 + t * 2 + k;
        g_xs[o]  = v;
        g_acc[o] = v;
    }
}

// push-scatter: acc[dst] += xs[src], 20 floats per edge, 5 float4-chunks
__global__ void k_scatter(const int* __restrict__ ei) {
    int idx = blockIdx.x * blockDim.x + threadIdx.x;
    if (idx >= NE * 5) return;
    int e = idx / 5;
    int q = idx - e * 5;
    int s = ei[e];
    int d = ei[NE + e];
    float4 v = *(const float4*)&g_xs[s * 20 + q * 4];
    float* a = &g_acc[d * 20 + q * 4];
    atomicAdd(a + 0, v.x);
    atomicAdd(a + 1, v.y);
    atomicAdd(a + 2, v.z);
    atomicAdd(a + 3, v.w);
}

// ---------------- fused GCN-finish + 2-layer LSTM + output ----------------
__device__ __forceinline__ float sigf(float x) {
    return __fdividef(1.0f, 1.0f + __expf(-x));
}
__device__ __forceinline__ float tanh_f(float x) {
    return 2.0f * sigf(2.0f * x) - 1.0f;
}

// one k-step of the register-tiled GEMM: 4 LDS.128, 64 FMA
__device__ __forceinline__ void gemm_step(const float* __restrict__ wsrow,
                                          const float* __restrict__ vrow,
                                          int ubase, int nbase,
                                          float a0[4][8], float a1[4][8]) {
    float4 w0 = *(const float4*)(wsrow + ubase);
    float4 w1 = *(const float4*)(wsrow + ubase + 4);
    float4 x0 = *(const float4*)(vrow + nbase);
    float4 x1 = *(const float4*)(vrow + nbase + 4);
    float xv[8] = {x0.x, x0.y, x0.z, x0.w, x1.x, x1.y, x1.z, x1.w};
    float wv0[4] = {w0.x, w0.y, w0.z, w0.w};
    float wv1[4] = {w1.x, w1.y, w1.z, w1.w};
#pragma unroll
    for (int ty = 0; ty < 4; ty++) {
#pragma unroll
        for (int j = 0; j < 8; j++) {
            a0[ty][j] = fmaf(wv0[ty], xv[j], a0[ty][j]);
            a1[ty][j] = fmaf(wv1[ty], xv[j], a1[ty][j]);
        }
    }
}

__device__ __forceinline__ void lstm_act(const float a[4][8],
                                         const float* __restrict__ bias,
                                         int ucol, float c[8], float h[8]) {
    float bi = bias[ucol + 0];
    float bf = bias[ucol + 1];
    float bg = bias[ucol + 2];
    float bo = bias[ucol + 3];
#pragma unroll
    for (int j = 0; j < 8; j++) {
        float iv = sigf(a[0][j] + bi);
        float fv = sigf(a[1][j] + bf);
        float gv = tanh_f(a[2][j] + bg);
        float ov = sigf(a[3][j] + bo);
        c[j] = fv * c[j] + iv * gv;
        h[j] = ov * tanh_f(c[j]);
    }
}

// smem layout (in floats)
#define O_WS0   0                    // [48][128]
#define O_WS1   (48 * 128)           // [64][128]  -> 6144
#define O_B0    (O_WS1 + 64 * 128)   // 14336, [128]
#define O_B1    (O_B0 + 128)         // 14464
#define O_OW    (O_B1 + 128)         // 14592, [32]
#define O_INB   (O_OW + 80)          // 14672, [10][16][128]
#define O_H0    (O_INB + T_STEPS * 16 * 128)  // 35152, [32][128]
#define O_H1    (O_H0 + 32 * 128)    // 39248
#define SM_FLOATS (O_H1 + 32 * 128)  // 43344
#define SM_BYTES  (SM_FLOATS * 4)    // 173376

__global__ __launch_bounds__(NTHR, 1)
void k_main(const float* __restrict__ wih0, const float* __restrict__ whh0,
            const float* __restrict__ bih0, const float* __restrict__ bhh0,
            const float* __restrict__ wih1, const float* __restrict__ whh1,
            const float* __restrict__ bih1, const float* __restrict__ bhh1,
            const float* __restrict__ gw,   const float* __restrict__ gb,
            const float* __restrict__ ow,   const float* __restrict__ ob,
            float* __restrict__ out) {
    extern __shared__ float sm[];
    float* ws0   = sm + O_WS0;
    float* ws1   = sm + O_WS1;
    float* bias0 = sm + O_B0;
    float* bias1 = sm + O_B1;
    float* outw  = sm + O_OW;
    float* inb   = sm + O_INB;
    float* h0b   = sm + O_H0;
    float* h1b   = sm + O_H1;

    int tid   = threadIdx.x;
    int node0 = blockIdx.x * BN;

    // ---- prologue: weights reordered into [k][unit*4 + gatetype] ----
    for (int idx = tid; idx < 48 * 128; idx += NTHR) {
        int k = idx >> 7, c = idx & 127;
        int u = c >> 2, ty = c & 3;
        int row = ty * 32 + u;                      // torch gate order i,f,g,o
        ws0[idx] = (k < 16) ? wih0[row * 16 + k] : whh0[row * 32 + (k - 16)];
    }
    for (int idx = tid; idx < 64 * 128; idx += NTHR) {
        int k = idx >> 7, c = idx & 127;
        int u = c >> 2, ty = c & 3;
        int row = ty * 32 + u;
        ws1[idx] = (k < 32) ? wih1[row * 32 + k] : whh1[row * 32 + (k - 32)];
    }
    if (tid < 128) {
        int u = tid >> 2, ty = tid & 3;
        int row = ty * 32 + u;
        bias0[tid] = bih0[row] + bhh0[row];
        bias1[tid] = bih1[row] + bhh1[row];
    }
    if (tid < 32) outw[tid] = ow[tid];
    for (int idx = tid; idx < 32 * 128; idx += NTHR) { h0b[idx] = 0.0f; h1b[idx] = 0.0f; }

    // ---- finish GCN for this tile: relu(dinv*(acc@Wg^T)+bg) -> inb[t][f][nl]
    for (int idx = tid; idx < BN * T_STEPS; idx += NTHR) {
        int nl = idx & (BN - 1);
        int t  = idx >> 7;
        int n  = node0 + nl;
        if (n >= NN) n = NN - 1;                    // clamp (tail block)
        float dv = g_dinv[n];
        float a0 = g_acc[n * 20 + t * 2 + 0] * dv;
        float a1 = g_acc[n * 20 + t * 2 + 1] * dv;
#pragma unroll
        for (int f = 0; f < 16; f++) {
            float v = a0 * gw[f * 2] + a1 * gw[f * 2 + 1] + gb[f];
            inb[(t * 16 + f) * 128 + nl] = fmaxf(v, 0.0f);
        }
    }
    __syncthreads();

    // ---- main time loop ----
    int up = tid >> 4;          // 0..15 unit-pair
    int ng = tid & 15;          // 0..15 node-group (8 nodes)
    int ubase = up * 8;         // column offset into ws rows (units up*2, up*2+1)
    int nbase = ng * 8;

    float c0a[8] = {}, c0b[8] = {};   // cell state layer0, units up*2 / up*2+1
    float c1a[8] = {}, c1b[8] = {};   // cell state layer1
    float outb = ob[0];

    for (int t = 0; t < T_STEPS; t++) {
        float a0[4][8], a1[4][8];
#pragma unroll
        for (int ty = 0; ty < 4; ty++)
#pragma unroll
            for (int j = 0; j < 8; j++) { a0[ty][j] = 0.0f; a1[ty][j] = 0.0f; }

        // ---- layer0 GEMM: gates = in_t @ Wih0^T + h0 @ Whh0^T ----
        const float* inT = inb + t * 16 * 128;
#pragma unroll 2
        for (int k = 0; k < 16; k++)
            gemm_step(ws0 + k * 128, inT + k * 128, ubase, nbase, a0, a1);
#pragma unroll 2
        for (int k = 0; k < 32; k++)
            gemm_step(ws0 + (16 + k) * 128, h0b + k * 128, ubase, nbase, a0, a1);
        __syncthreads();    // all reads of h0b done

        {
            float hA[8], hB[8];
            lstm_act(a0, bias0, ubase,     c0a, hA);
            lstm_act(a1, bias0, ubase + 4, c0b, hB);
            int u0 = up * 2;
            *(float4*)(h0b + u0 * 128 + nbase)           = make_float4(hA[0], hA[1], hA[2], hA[3]);
            *(float4*)(h0b + u0 * 128 + nbase + 4)       = make_float4(hA[4], hA[5], hA[6], hA[7]);
            *(float4*)(h0b + (u0 + 1) * 128 + nbase)     = make_float4(hB[0], hB[1], hB[2], hB[3]);
            *(float4*)(h0b + (u0 + 1) * 128 + nbase + 4) = make_float4(hB[4], hB[5], hB[6], hB[7]);
        }
        __syncthreads();    // new h0 visible

        // ---- layer1 GEMM: gates = h0 @ Wih1^T + h1 @ Whh1^T ----
#pragma unroll
        for (int ty = 0; ty < 4; ty++)
#pragma unroll
            for (int j = 0; j < 8; j++) { a0[ty][j] = 0.0f; a1[ty][j] = 0.0f; }
#pragma unroll 2
        for (int k = 0; k < 32; k++)
            gemm_step(ws1 + k * 128, h0b + k * 128, ubase, nbase, a0, a1);
#pragma unroll 2
        for (int k = 0; k < 32; k++)
            gemm_step(ws1 + (32 + k) * 128, h1b + k * 128, ubase, nbase, a0, a1);
        __syncthreads();    // all reads of h1b done

        {
            float hA[8], hB[8];
            lstm_act(a0, bias1, ubase,     c1a, hA);
            lstm_act(a1, bias1, ubase + 4, c1b, hB);
            int u0 = up * 2;
            *(float4*)(h1b + u0 * 128 + nbase)           = make_float4(hA[0], hA[1], hA[2], hA[3]);
            *(float4*)(h1b + u0 * 128 + nbase + 4)       = make_float4(hA[4], hA[5], hA[6], hA[7]);
            *(float4*)(h1b + (u0 + 1) * 128 + nbase)     = make_float4(hB[0], hB[1], hB[2], hB[3]);
            *(float4*)(h1b + (u0 + 1) * 128 + nbase + 4) = make_float4(hB[4], hB[5], hB[6], hB[7]);
        }
        __syncthreads();    // new h1 visible

        // ---- output projection out[t][n] = h1 . out_w + out_b ----
        if (tid < BN) {
            int n = node0 + tid;
            if (n < NN) {
                float s = outb;
#pragma unroll
                for (int u = 0; u < 32; u++) s = fmaf(h1b[u * 128 + tid], outw[u], s);
                out[t * NN + n] = s;
            }
        }
        // h1b reads above finish before next iteration's h1b-write barrier
    }
}

// ---------------- launcher ----------------
extern "C" void kernel_launch(void* const* d_in, const int* in_sizes, int n_in,
                              void* d_out, int out_size) {
    const float* x    = (const float*)d_in[0];
    const int*   ei   = (const int*)  d_in[1];
    const float* gw   = (const float*)d_in[2];
    const float* gb   = (const float*)d_in[3];
    const float* wih0 = (const float*)d_in[4];
    const float* whh0 = (const float*)d_in[5];
    const float* bih0 = (const float*)d_in[6];
    const float* bhh0 = (const float*)d_in[7];
    const float* wih1 = (const float*)d_in[8];
    const float* whh1 = (const float*)d_in[9];
    const float* bih1 = (const float*)d_in[10];
    const float* bhh1 = (const float*)d_in[11];
    const float* ow   = (const float*)d_in[12];
    const float* ob   = (const float*)d_in[13];
    float* out = (float*)d_out;

    cudaFuncSetAttribute(k_main, cudaFuncAttributeMaxDynamicSharedMemorySize, SM_BYTES);

    k_init_deg<<<(NN + 255) / 256, 256>>>();
    k_count   <<<(NE + 255) / 256, 256>>>(ei);
    k_dinv    <<<(NN + 255) / 256, 256>>>();
    k_xs      <<<(T_STEPS * NN * F_INN + 255) / 256, 256>>>(x);
    k_scatter <<<(NE * 5 + 255) / 256, 256>>>(ei);
    k_main    <<<(NN + BN - 1) / BN, NTHR, SM_BYTES>>>(
        wih0, whh0, bih0, bhh0, wih1, whh1, bih1, bhh1, gw, gb, ow, ob, out);
}